// round 1
// baseline (speedup 1.0000x reference)
#include <cuda_runtime.h>
#include <cstdint>

// Shapes (fixed by the problem): B=4096, D=1024, H=4096, L=8
// out = a + x @ (V^T V) + sum_l s_l * (tanh(Z_l) @ W_l),  Z_l = x @ W_l^T + b_l
// s_l[b] = sum_h logcosh(Z_l[b,h])

#define BM 128
#define BN 128
#define BK 16
#define TM 8
#define TN 8

// Scratch (static device globals: allocation-free per harness rules)
__device__ float g_Vsq[1024 * 1024];        // 4 MB   : V^T V
__device__ float g_Z[4096 * 4096];          // 64 MB  : Z_l then tanh(Z_l), reused per l
__device__ float g_part[4096 * 32];         // 512 KB : per-(row, n-tile) logcosh partials
__device__ float g_s[4096];                 // s_l[b]

// tanh(z) and logcosh(z) from one exp:
//   e = exp(-2|z|); tanh = sign(z)*(1-e)/(1+e); logcosh = |z| + log(1+e) - ln2
__device__ __forceinline__ float tanh_lc(float z, float &lc) {
    float az = fabsf(z);
    float e  = __expf(-2.0f * az);
    float t  = __fdividef(1.0f - e, 1.0f + e);
    t = copysignf(t, z);
    lc = az + __logf(1.0f + e) - 0.6931471805599453f;
    return t;
}

// Generic tiled SGEMM.
// AT=0: A is [M,K] row-major (lda = row stride). AT=1: A is [K,M] (lda = row stride).
// BT=0: B is [K,N] row-major.                    BT=1: B is [N,K] row-major.
// EPI=0: C = acc
// EPI=1: C = acc + bias[col]
// EPI=2: C += svec[row] * acc
// EPI=3: z = acc + bias[col]; C = tanh(z); part[row][blockIdx.x] = sum_cols logcosh(z)
template<int AT, int BT, int EPI>
__global__ __launch_bounds__(256, 2)
void gemm_k(int M, int N, int K,
            const float* __restrict__ A, int lda,
            const float* __restrict__ Bp, int ldb,
            float* __restrict__ C, int ldc,
            const float* __restrict__ bias,
            const float* __restrict__ svec,
            float* __restrict__ part, int npart)
{
    __shared__ float As[BK][BM];
    __shared__ float Bs[BK][BN];

    const int tid = threadIdx.x;
    const int tx = tid & 15;        // 0..15 -> N direction
    const int ty = tid >> 4;        // 0..15 -> M direction
    const int bm = blockIdx.y * BM;
    const int bn = blockIdx.x * BN;

    float acc[TM][TN];
#pragma unroll
    for (int i = 0; i < TM; i++)
#pragma unroll
        for (int j = 0; j < TN; j++) acc[i][j] = 0.0f;

    for (int k0 = 0; k0 < K; k0 += BK) {
        // ---- load A tile into As[k][m] ----
        if (AT == 0) {
            // A[M,K] row-major: read float4 along k, scatter-transpose
            const int r = tid >> 2;              // 0..63
            const int c = (tid & 3) << 2;        // 0,4,8,12
#pragma unroll
            for (int i = 0; i < 2; i++) {
                const int row = r + i * 64;
                const float4 v = *(const float4*)(A + (size_t)(bm + row) * lda + k0 + c);
                As[c + 0][row] = v.x;
                As[c + 1][row] = v.y;
                As[c + 2][row] = v.z;
                As[c + 3][row] = v.w;
            }
        } else {
            // A[K,M]: contiguous along m, direct float4
            const int r = tid >> 5;              // 0..7
            const int c = (tid & 31) << 2;       // 0..124
#pragma unroll
            for (int i = 0; i < 2; i++) {
                const int k = r + i * 8;
                *(float4*)&As[k][c] = *(const float4*)(A + (size_t)(k0 + k) * lda + bm + c);
            }
        }
        // ---- load B tile into Bs[k][n] ----
        if (BT == 0) {
            // B[K,N] row-major: contiguous along n
            const int r = tid >> 5;
            const int c = (tid & 31) << 2;
#pragma unroll
            for (int i = 0; i < 2; i++) {
                const int k = r + i * 8;
                *(float4*)&Bs[k][c] = *(const float4*)(Bp + (size_t)(k0 + k) * ldb + bn + c);
            }
        } else {
            // B[N,K] row-major: read float4 along k, scatter-transpose
            const int r = tid >> 2;
            const int c = (tid & 3) << 2;
#pragma unroll
            for (int i = 0; i < 2; i++) {
                const int row = r + i * 64;
                const float4 v = *(const float4*)(Bp + (size_t)(bn + row) * ldb + k0 + c);
                Bs[c + 0][row] = v.x;
                Bs[c + 1][row] = v.y;
                Bs[c + 2][row] = v.z;
                Bs[c + 3][row] = v.w;
            }
        }
        __syncthreads();

#pragma unroll
        for (int k = 0; k < BK; k++) {
            float ra[TM], rb[TN];
            *(float4*)&ra[0] = *(const float4*)&As[k][ty * TM];
            *(float4*)&ra[4] = *(const float4*)&As[k][ty * TM + 4];
            *(float4*)&rb[0] = *(const float4*)&Bs[k][tx * TN];
            *(float4*)&rb[4] = *(const float4*)&Bs[k][tx * TN + 4];
#pragma unroll
            for (int i = 0; i < TM; i++)
#pragma unroll
                for (int j = 0; j < TN; j++)
                    acc[i][j] += ra[i] * rb[j];
        }
        __syncthreads();
    }

    // ---- epilogue ----
    const int col0 = bn + tx * TN;
#pragma unroll
    for (int i = 0; i < TM; i++) {
        const int row = bm + ty * TM + i;
        float* crow = C + (size_t)row * ldc + col0;

        if (EPI == 0) {
            float4 v0 = make_float4(acc[i][0], acc[i][1], acc[i][2], acc[i][3]);
            float4 v1 = make_float4(acc[i][4], acc[i][5], acc[i][6], acc[i][7]);
            *(float4*)(crow)     = v0;
            *(float4*)(crow + 4) = v1;
        } else if (EPI == 1) {
            float4 b0 = *(const float4*)(bias + col0);
            float4 b1 = *(const float4*)(bias + col0 + 4);
            float4 v0 = make_float4(acc[i][0] + b0.x, acc[i][1] + b0.y,
                                    acc[i][2] + b0.z, acc[i][3] + b0.w);
            float4 v1 = make_float4(acc[i][4] + b1.x, acc[i][5] + b1.y,
                                    acc[i][6] + b1.z, acc[i][7] + b1.w);
            *(float4*)(crow)     = v0;
            *(float4*)(crow + 4) = v1;
        } else if (EPI == 2) {
            const float sv = svec[row];
            float4 o0 = *(const float4*)(crow);
            float4 o1 = *(const float4*)(crow + 4);
            o0.x += sv * acc[i][0]; o0.y += sv * acc[i][1];
            o0.z += sv * acc[i][2]; o0.w += sv * acc[i][3];
            o1.x += sv * acc[i][4]; o1.y += sv * acc[i][5];
            o1.z += sv * acc[i][6]; o1.w += sv * acc[i][7];
            *(float4*)(crow)     = o0;
            *(float4*)(crow + 4) = o1;
        } else { // EPI == 3
            float4 b0 = *(const float4*)(bias + col0);
            float4 b1 = *(const float4*)(bias + col0 + 4);
            float zb[8];
            zb[0] = acc[i][0] + b0.x; zb[1] = acc[i][1] + b0.y;
            zb[2] = acc[i][2] + b0.z; zb[3] = acc[i][3] + b0.w;
            zb[4] = acc[i][4] + b1.x; zb[5] = acc[i][5] + b1.y;
            zb[6] = acc[i][6] + b1.z; zb[7] = acc[i][7] + b1.w;
            float lcsum = 0.0f;
            float t[8];
#pragma unroll
            for (int j = 0; j < 8; j++) {
                float lc;
                t[j] = tanh_lc(zb[j], lc);
                lcsum += lc;
            }
            *(float4*)(crow)     = make_float4(t[0], t[1], t[2], t[3]);
            *(float4*)(crow + 4) = make_float4(t[4], t[5], t[6], t[7]);
            // reduce lcsum across the 16 tx-lanes (contiguous within warp halves)
            lcsum += __shfl_xor_sync(0xffffffffu, lcsum, 1);
            lcsum += __shfl_xor_sync(0xffffffffu, lcsum, 2);
            lcsum += __shfl_xor_sync(0xffffffffu, lcsum, 4);
            lcsum += __shfl_xor_sync(0xffffffffu, lcsum, 8);
            if (tx == 0)
                part[(size_t)row * npart + blockIdx.x] = lcsum;
        }
    }
}

__global__ void reduce_partials(const float* __restrict__ part,
                                float* __restrict__ s, int np, int nrows)
{
    int b = blockIdx.x * blockDim.x + threadIdx.x;
    if (b >= nrows) return;
    float sum = 0.0f;
    for (int j = 0; j < np; j++) sum += part[(size_t)b * np + j];
    s[b] = sum;
}

extern "C" void kernel_launch(void* const* d_in, const int* in_sizes, int n_in,
                              void* d_out, int out_size)
{
    const float* x  = (const float*)d_in[0];   // [B, D]
    const float* Wk = (const float*)d_in[1];   // [L, H, D]
    const float* bk = (const float*)d_in[2];   // [L, H]
    const float* V  = (const float*)d_in[3];   // [H, D]
    const float* a  = (const float*)d_in[4];   // [D]
    float* out = (float*)d_out;                // [B, D]

    const int D = in_sizes[4];                 // 1024
    const int B = in_sizes[0] / D;             // 4096
    const int H = in_sizes[3] / D;             // 4096
    const int L = in_sizes[2] / H;             // 8

    float *pVsq, *pZ, *pPart, *pS;
    cudaGetSymbolAddress((void**)&pVsq,  g_Vsq);
    cudaGetSymbolAddress((void**)&pZ,    g_Z);
    cudaGetSymbolAddress((void**)&pPart, g_part);
    cudaGetSymbolAddress((void**)&pS,    g_s);

    const dim3 thr(256);
    const int NP = H / BN;  // 32 n-tiles per row for the Z GEMM

    // K1: Vsq = V^T V      (A = V as [K=H, M=D], B = V as [K=H, N=D])
    gemm_k<1, 0, 0><<<dim3(D / BN, D / BM), thr>>>(
        D, D, H, V, D, V, D, pVsq, D, nullptr, nullptr, nullptr, 0);

    // K2: out = a + x @ Vsq
    gemm_k<0, 0, 1><<<dim3(D / BN, B / BM), thr>>>(
        B, D, D, x, D, pVsq, D, out, D, a, nullptr, nullptr, 0);

    for (int l = 0; l < L; l++) {
        const float* Wl = Wk + (size_t)l * H * D;   // [H, D]
        const float* bl = bk + (size_t)l * H;       // [H]

        // K3: Z = x @ Wl^T + bl ; store tanh(Z) in g_Z, logcosh partials in g_part
        gemm_k<0, 1, 3><<<dim3(H / BN, B / BM), thr>>>(
            B, H, D, x, D, Wl, D, pZ, H, bl, nullptr, pPart, NP);

        // K4: s[b] = sum of partials
        reduce_partials<<<(B + 255) / 256, 256>>>(pPart, pS, NP, B);

        // K5: out += s[b] * (tanh(Z) @ Wl)
        gemm_k<0, 0, 2><<<dim3(D / BN, B / BM), thr>>>(
            B, D, H, pZ, H, Wl, D, out, D, nullptr, pS, nullptr, 0);
    }
}